// round 6
// baseline (speedup 1.0000x reference)
#include <cuda_runtime.h>
#include <cuda_fp16.h>
#include <cstdint>

// ---------------------------------------------------------------------------
// Problem constants
// ---------------------------------------------------------------------------
#define BATCH   2
#define NRES    1280
#define KNBR    48
#define C_NODE  384
#define C_EDGE  128
#define C_OUT_  128
#define C_BIAS  192
#define HID     512
#define NODES   (BATCH * NRES)        // 2560
#define MROWS   (NODES * KNBR)        // 122880 = 960 * 128

// ---------------------------------------------------------------------------
// Scratch (static device globals; allocation-free per harness rules)
// ---------------------------------------------------------------------------
__device__ float  g_n[NODES * C_BIAS];
__device__ __half g_X [(size_t)MROWS * HID];
__device__ __half g_H [(size_t)MROWS * HID];
__device__ __half g_H2[(size_t)MROWS * HID];     // holds relu(h@W2+b2) + x
__device__ __half g_W1h[HID * HID];              // [K=512][N=512]
__device__ __half g_W2h[HID * HID];
__device__ __half g_Wfh[HID * C_OUT_];           // [K=512][N=128]

// ---------------------------------------------------------------------------
// fp32 -> fp16 weight conversion
// ---------------------------------------------------------------------------
__global__ void f2h_kernel(const float* __restrict__ src, __half* __restrict__ dst, int n) {
    for (int i = blockIdx.x * blockDim.x + threadIdx.x; i < n; i += gridDim.x * blockDim.x)
        dst[i] = __float2half_rn(src[i]);
}

// ---------------------------------------------------------------------------
// n = node_emb @ Wi + bi   [2560,384]@[384,192]
// 160 blocks x 384 threads; 16 rows/block. Thread t: col j = t%192,
// row-half rh = t/192, computes 8 outputs (rows rh*8..rh*8+7).
// Wi traffic per block = 2 x 294KB (one read per row-half) -> 94MB total.
// ---------------------------------------------------------------------------
__global__ void node_proj_kernel(const float* __restrict__ node,
                                 const float* __restrict__ Wi,
                                 const float* __restrict__ bi) {
    __shared__ float s[16 * C_NODE];              // 24.6 KB
    const int t  = threadIdx.x;                   // 0..383
    const int r0 = blockIdx.x * 16;
    {
        const float4* src = reinterpret_cast<const float4*>(node + (size_t)r0 * C_NODE);
        float4* ds = reinterpret_cast<float4*>(s);
#pragma unroll
        for (int i = 0; i < 4; i++) ds[i * 384 + t] = src[i * 384 + t];
    }
    __syncthreads();
    const int j  = t % C_BIAS;
    const int rh = t / C_BIAS;                    // 0 or 1
    const float* sr = s + rh * 8 * C_NODE;
    float acc[8];
#pragma unroll
    for (int r = 0; r < 8; r++) acc[r] = 0.f;
#pragma unroll 4
    for (int k = 0; k < C_NODE; k++) {
        const float w = Wi[k * C_BIAS + j];
#pragma unroll
        for (int r = 0; r < 8; r++) acc[r] += sr[r * C_NODE + k] * w;
    }
    const float bv = bi[j];
#pragma unroll
    for (int r = 0; r < 8; r++)
        g_n[(size_t)(r0 + rh * 8 + r) * C_BIAS + j] = acc[r] + bv;
}

// ---------------------------------------------------------------------------
// Build X[b,i,k] = concat(edge(128), n[b,i](192), n[b,E_idx](192)) as fp16.
// ---------------------------------------------------------------------------
__global__ void build_x_kernel(const float* __restrict__ edge, const int* __restrict__ Eidx) {
    const int bi = blockIdx.x;
    __shared__ __align__(16) __half s_self[C_BIAS];
    __shared__ int s_idx[KNBR];
    const int t = threadIdx.x;
    if (t < C_BIAS) s_self[t] = __float2half_rn(g_n[(size_t)bi * C_BIAS + t]);
    if (t < KNBR)   s_idx[t]  = Eidx[bi * KNBR + t];
    __syncthreads();

    const int b = bi / NRES;
    const float* nb = g_n + (size_t)b * NRES * C_BIAS;
    const float* er = edge + (size_t)bi * KNBR * C_EDGE;
    __half* xr = g_X + (size_t)bi * KNBR * HID;

    for (int g = t; g < KNBR * (HID / 8); g += 256) {
        const int k  = g >> 6;
        const int c8 = (g & 63) * 8;
        uint4 w;
        if (c8 < C_EDGE) {
            const float4 a  = *reinterpret_cast<const float4*>(er + k * C_EDGE + c8);
            const float4 bq = *reinterpret_cast<const float4*>(er + k * C_EDGE + c8 + 4);
            __half2 h0 = __floats2half2_rn(a.x, a.y),  h1 = __floats2half2_rn(a.z, a.w);
            __half2 h2 = __floats2half2_rn(bq.x, bq.y), h3 = __floats2half2_rn(bq.z, bq.w);
            w = make_uint4(*(uint32_t*)&h0, *(uint32_t*)&h1, *(uint32_t*)&h2, *(uint32_t*)&h3);
        } else if (c8 < C_EDGE + C_BIAS) {
            w = *reinterpret_cast<const uint4*>(s_self + (c8 - C_EDGE));
        } else {
            const float* src = nb + (size_t)s_idx[k] * C_BIAS + (c8 - C_EDGE - C_BIAS);
            const float4 a  = *reinterpret_cast<const float4*>(src);
            const float4 bq = *reinterpret_cast<const float4*>(src + 4);
            __half2 h0 = __floats2half2_rn(a.x, a.y),  h1 = __floats2half2_rn(a.z, a.w);
            __half2 h2 = __floats2half2_rn(bq.x, bq.y), h3 = __floats2half2_rn(bq.z, bq.w);
            w = make_uint4(*(uint32_t*)&h0, *(uint32_t*)&h1, *(uint32_t*)&h2, *(uint32_t*)&h3);
        }
        *reinterpret_cast<uint4*>(xr + k * HID + c8) = w;
    }
}

// ---------------------------------------------------------------------------
// GEMM: C[M, Nc] = act( A @ Bw + bias ) [+ Xres],  K = KT*64 (lda=512, ldb=Nc).
// fp16 in / fp32 accumulate, mma.sync m16n8k16.
// BM=128, BN=BN_ (128 or 256), BK=64; BN_*2 threads, warp tile 32x64.
// 3-stage cp.async pipeline, one __syncthreads per K-tile.
// ADDX : epilogue out = relu(acc+bias) + Xres   (residual fold)
// LN_OUT: stage acc+bias to smem, fused LayerNorm (Nc==128, BN_==128).
// ---------------------------------------------------------------------------
template <int BN_, bool RELU, bool LN_OUT, bool ADDX>
__global__ void __launch_bounds__(BN_ * 2, (BN_ == 128) ? 2 : 1)
gemm_kernel(const __half* __restrict__ A, const __half* __restrict__ Bw,
            const float* __restrict__ bias, const __half* __restrict__ Xres,
            const float* __restrict__ gamma, const float* __restrict__ beta,
            __half* __restrict__ Ch, float* __restrict__ Cf,
            int Nc, int KT) {
    constexpr int BM = 128, BK = 64;
    constexpr int TPB = BN_ * 2;
    constexpr int WN_CNT = BN_ / 64;
    constexpr int LDA = BK + 8;                   // 72
    constexpr int LDB = BN_ + 8;
    constexpr int BSEG = BN_ / 8;                 // B segs per row
    extern __shared__ __align__(16) char smem_raw[];
    __half (*As)[BM][LDA] = reinterpret_cast<__half (*)[BM][LDA]>(smem_raw);
    __half (*Bs)[BK][LDB] = reinterpret_cast<__half (*)[BK][LDB]>(smem_raw + 3 * BM * LDA * 2);

    const int t = threadIdx.x, lane = t & 31, wid = t >> 5;
    const int bm = blockIdx.y, bn = blockIdx.x;
    const int wm = (wid / WN_CNT) * 32, wn = (wid % WN_CNT) * 64;

    float acc[2][8][4];
#pragma unroll
    for (int a = 0; a < 2; a++)
#pragma unroll
        for (int b = 0; b < 8; b++)
#pragma unroll
            for (int c = 0; c < 4; c++) acc[a][b][c] = 0.f;

    auto load_tiles = [&](int st, int kt) {
        const int k0 = kt * BK;
#pragma unroll
        for (int j = 0; j < 1024 / TPB; j++) {            // A: 1024 16B segs
            const int idx = j * TPB + t;
            const int r = idx >> 3, sg = idx & 7;
            const __half* src = A + ((size_t)bm * BM + r) * HID + k0 + sg * 8;
            const uint32_t dst = (uint32_t)__cvta_generic_to_shared(&As[st][r][sg * 8]);
            asm volatile("cp.async.cg.shared.global [%0], [%1], 16;\n" :: "r"(dst), "l"(src));
        }
#pragma unroll
        for (int j = 0; j < (BK * BSEG) / TPB; j++) {     // B: 64*BSEG segs
            const int idx = j * TPB + t;
            const int r = idx / BSEG, sg = idx % BSEG;
            const __half* src = Bw + (size_t)(k0 + r) * Nc + bn * BN_ + sg * 8;
            const uint32_t dst = (uint32_t)__cvta_generic_to_shared(&Bs[st][r][sg * 8]);
            asm volatile("cp.async.cg.shared.global [%0], [%1], 16;\n" :: "r"(dst), "l"(src));
        }
    };

    load_tiles(0, 0);
    asm volatile("cp.async.commit_group;\n");
    if (KT > 1) {
        load_tiles(1, 1);
        asm volatile("cp.async.commit_group;\n");
    }

    int st = 0;
    for (int kt = 0; kt < KT; kt++, st = (st == 2) ? 0 : st + 1) {
        if (kt < KT - 1) asm volatile("cp.async.wait_group 1;\n");
        else             asm volatile("cp.async.wait_group 0;\n");
        __syncthreads();
        if (kt + 2 < KT) {
            const int st2 = (st + 2 > 2) ? st - 1 : st + 2;
            load_tiles(st2, kt + 2);
            asm volatile("cp.async.commit_group;\n");
        }
#pragma unroll
        for (int kk = 0; kk < 4; kk++) {
            uint32_t afr[2][4];
#pragma unroll
            for (int mi = 0; mi < 2; mi++) {
                const uint32_t addr = (uint32_t)__cvta_generic_to_shared(
                    &As[st][wm + mi * 16 + (lane & 15)][kk * 16 + ((lane >> 4) << 3)]);
                asm volatile("ldmatrix.sync.aligned.m8n8.x4.shared.b16 {%0,%1,%2,%3}, [%4];\n"
                             : "=r"(afr[mi][0]), "=r"(afr[mi][1]), "=r"(afr[mi][2]), "=r"(afr[mi][3])
                             : "r"(addr));
            }
            uint32_t bfr[4][4];
#pragma unroll
            for (int nj = 0; nj < 4; nj++) {
                const uint32_t addr = (uint32_t)__cvta_generic_to_shared(
                    &Bs[st][kk * 16 + (lane & 15)][wn + nj * 16 + ((lane >> 4) << 3)]);
                asm volatile("ldmatrix.sync.aligned.m8n8.x4.trans.shared.b16 {%0,%1,%2,%3}, [%4];\n"
                             : "=r"(bfr[nj][0]), "=r"(bfr[nj][1]), "=r"(bfr[nj][2]), "=r"(bfr[nj][3])
                             : "r"(addr));
            }
#pragma unroll
            for (int mi = 0; mi < 2; mi++)
#pragma unroll
                for (int n8 = 0; n8 < 8; n8++) {
                    const uint32_t b0 = bfr[n8 >> 1][(n8 & 1) * 2 + 0];
                    const uint32_t b1 = bfr[n8 >> 1][(n8 & 1) * 2 + 1];
                    asm volatile(
                        "mma.sync.aligned.m16n8k16.row.col.f32.f16.f16.f32 "
                        "{%0,%1,%2,%3}, {%4,%5,%6,%7}, {%8,%9}, {%0,%1,%2,%3};\n"
                        : "+f"(acc[mi][n8][0]), "+f"(acc[mi][n8][1]),
                          "+f"(acc[mi][n8][2]), "+f"(acc[mi][n8][3])
                        : "r"(afr[mi][0]), "r"(afr[mi][1]), "r"(afr[mi][2]), "r"(afr[mi][3]),
                          "r"(b0), "r"(b1));
                }
        }
    }

    const int lr = lane >> 2, lc = (lane & 3) * 2;
    if (!LN_OUT) {
#pragma unroll
        for (int mi = 0; mi < 2; mi++) {
#pragma unroll
            for (int n8 = 0; n8 < 8; n8++) {
                const int row = bm * BM + wm + mi * 16 + lr;
                const int col = bn * BN_ + wn + n8 * 8 + lc;
                const float bv0 = bias[col], bv1 = bias[col + 1];
                float v0 = acc[mi][n8][0] + bv0;
                float v1 = acc[mi][n8][1] + bv1;
                float v2 = acc[mi][n8][2] + bv0;
                float v3 = acc[mi][n8][3] + bv1;
                if (RELU) {
                    v0 = fmaxf(v0, 0.f); v1 = fmaxf(v1, 0.f);
                    v2 = fmaxf(v2, 0.f); v3 = fmaxf(v3, 0.f);
                }
                if (ADDX) {
                    const __half2 x0 = *reinterpret_cast<const __half2*>(
                        Xres + (size_t)row * Nc + col);
                    const __half2 x1 = *reinterpret_cast<const __half2*>(
                        Xres + (size_t)(row + 8) * Nc + col);
                    v0 += __low2float(x0); v1 += __high2float(x0);
                    v2 += __low2float(x1); v3 += __high2float(x1);
                }
                *reinterpret_cast<__half2*>(Ch + (size_t)row * Nc + col)       = __floats2half2_rn(v0, v1);
                *reinterpret_cast<__half2*>(Ch + (size_t)(row + 8) * Nc + col) = __floats2half2_rn(v2, v3);
            }
        }
    } else {
        // stage acc+bias to smem, fused LayerNorm (Nc == 128, bn == 0, TPB == 256)
        constexpr int LDY = 132;
        float* sY = reinterpret_cast<float*>(smem_raw);
        __syncthreads();
#pragma unroll
        for (int mi = 0; mi < 2; mi++) {
#pragma unroll
            for (int n8 = 0; n8 < 8; n8++) {
                const int r = wm + mi * 16 + lr;
                const int c = wn + n8 * 8 + lc;
                const float bv0 = bias[c], bv1 = bias[c + 1];
                *reinterpret_cast<float2*>(&sY[r * LDY + c]) =
                    make_float2(acc[mi][n8][0] + bv0, acc[mi][n8][1] + bv1);
                *reinterpret_cast<float2*>(&sY[(r + 8) * LDY + c]) =
                    make_float2(acc[mi][n8][2] + bv0, acc[mi][n8][3] + bv1);
            }
        }
        __syncthreads();
        const float4 gg = reinterpret_cast<const float4*>(gamma)[lane];
        const float4 bb = reinterpret_cast<const float4*>(beta)[lane];
#pragma unroll
        for (int rr = 0; rr < 16; rr++) {
            const int r = wid * 16 + rr;
            const float4 v = *reinterpret_cast<const float4*>(&sY[r * LDY + lane * 4]);
            float s  = v.x + v.y + v.z + v.w;
            float sq = v.x * v.x + v.y * v.y + v.z * v.z + v.w * v.w;
#pragma unroll
            for (int off = 16; off > 0; off >>= 1) {
                s  += __shfl_xor_sync(0xffffffffu, s, off);
                sq += __shfl_xor_sync(0xffffffffu, sq, off);
            }
            const float mu  = s * (1.f / 128.f);
            const float inv = rsqrtf(sq * (1.f / 128.f) - mu * mu + 1e-5f);
            float4 o;
            o.x = (v.x - mu) * inv * gg.x + bb.x;
            o.y = (v.y - mu) * inv * gg.y + bb.y;
            o.z = (v.z - mu) * inv * gg.z + bb.z;
            o.w = (v.w - mu) * inv * gg.w + bb.w;
            *reinterpret_cast<float4*>(Cf + (size_t)(bm * BM + r) * 128 + lane * 4) = o;
        }
    }
}

// ---------------------------------------------------------------------------
// Launch
// ---------------------------------------------------------------------------
extern "C" void kernel_launch(void* const* d_in, const int* in_sizes, int n_in,
                              void* d_out, int out_size) {
    const float* node  = (const float*)d_in[0];
    const float* edge  = (const float*)d_in[1];
    const int*   eidx  = (const int*)  d_in[2];
    const float* Wi    = (const float*)d_in[3];
    const float* bi    = (const float*)d_in[4];
    const float* W1    = (const float*)d_in[5];
    const float* b1    = (const float*)d_in[6];
    const float* W2    = (const float*)d_in[7];
    const float* b2    = (const float*)d_in[8];
    const float* Wf    = (const float*)d_in[9];
    const float* bf    = (const float*)d_in[10];
    const float* gamma = (const float*)d_in[11];
    const float* beta  = (const float*)d_in[12];
    float* out = (float*)d_out;

    void *pW1h, *pW2h, *pWfh, *pX, *pH, *pH2;
    cudaGetSymbolAddress(&pW1h, g_W1h);
    cudaGetSymbolAddress(&pW2h, g_W2h);
    cudaGetSymbolAddress(&pWfh, g_Wfh);
    cudaGetSymbolAddress(&pX,  g_X);
    cudaGetSymbolAddress(&pH,  g_H);
    cudaGetSymbolAddress(&pH2, g_H2);

    // dynamic smem: 3 stages of (As 128x72 + Bs 64x(BN+8)) fp16
    const int SMEM256 = 3 * (128 * 72 + 64 * 264) * 2;   // 156,672 B
    const int SMEM128 = 3 * (128 * 72 + 64 * 136) * 2;   // 107,520 B
    cudaFuncSetAttribute(gemm_kernel<256, true,  false, false>,
                         cudaFuncAttributeMaxDynamicSharedMemorySize, SMEM256);
    cudaFuncSetAttribute(gemm_kernel<256, true,  false, true>,
                         cudaFuncAttributeMaxDynamicSharedMemorySize, SMEM256);
    cudaFuncSetAttribute(gemm_kernel<128, false, true,  false>,
                         cudaFuncAttributeMaxDynamicSharedMemorySize, SMEM128);

    f2h_kernel<<<512, 256>>>(W1, (__half*)pW1h, HID * HID);
    f2h_kernel<<<512, 256>>>(W2, (__half*)pW2h, HID * HID);
    f2h_kernel<<<256, 256>>>(Wf, (__half*)pWfh, HID * C_OUT_);

    node_proj_kernel<<<NODES / 16, 384>>>(node, Wi, bi);
    build_x_kernel<<<NODES, 256>>>(edge, eidx);

    // h = relu(X @ W1 + b1)
    gemm_kernel<256, true, false, false><<<dim3(HID / 256, MROWS / 128), 512, SMEM256>>>(
        (const __half*)pX, (const __half*)pW1h, b1, nullptr,
        nullptr, nullptr, (__half*)pH, nullptr, HID, 8);
    // h2' = relu(h @ W2 + b2) + x      (residual folded into epilogue)
    gemm_kernel<256, true, false, true><<<dim3(HID / 256, MROWS / 128), 512, SMEM256>>>(
        (const __half*)pH, (const __half*)pW2h, b2, (const __half*)pX,
        nullptr, nullptr, (__half*)pH2, nullptr, HID, 8);
    // out = LN(h2' @ Wf + bf)          (single-A K=512, fused LN)
    gemm_kernel<128, false, true, false><<<dim3(1, MROWS / 128), 256, SMEM128>>>(
        (const __half*)pH2, (const __half*)pWfh, bf, nullptr,
        gamma, beta, nullptr, out, C_OUT_, 8);
}

// round 7
// speedup vs baseline: 1.5882x; 1.5882x over previous
#include <cuda_runtime.h>
#include <cuda_fp16.h>
#include <cstdint>

// ---------------------------------------------------------------------------
// Problem constants
// ---------------------------------------------------------------------------
#define BATCH   2
#define NRES    1280
#define KNBR    48
#define C_NODE  384
#define C_EDGE  128
#define C_OUT_  128
#define C_BIAS  192
#define HID     512
#define NODES   (BATCH * NRES)        // 2560
#define MROWS   (NODES * KNBR)        // 122880 = 960 * 128

// ---------------------------------------------------------------------------
// Scratch (static device globals; allocation-free per harness rules)
// ---------------------------------------------------------------------------
__device__ float  g_n[NODES * C_BIAS];
__device__ __half g_X [(size_t)MROWS * HID];
__device__ __half g_H [(size_t)MROWS * HID];
__device__ __half g_H2[(size_t)MROWS * HID];     // holds relu(h@W2+b2) + x
__device__ __half g_W1h[HID * HID];              // [K=512][N=512]
__device__ __half g_W2h[HID * HID];
__device__ __half g_Wfh[HID * C_OUT_];           // [K=512][N=128]

// ---------------------------------------------------------------------------
// fp32 -> fp16 weight conversion
// ---------------------------------------------------------------------------
__global__ void f2h_kernel(const float* __restrict__ src, __half* __restrict__ dst, int n) {
    for (int i = blockIdx.x * blockDim.x + threadIdx.x; i < n; i += gridDim.x * blockDim.x)
        dst[i] = __float2half_rn(src[i]);
}

// ---------------------------------------------------------------------------
// n = node_emb @ Wi + bi   [2560,384]@[384,192]
// 640 blocks x 384 threads; 4 rows/block. Thread t: col j = t%192,
// row-half rh = t/192 -> rows rh*2 .. rh*2+1 (2 accumulators).
// Wi L2 traffic = 640 x 294KB = 188MB; ~4 CTAs/SM for latency cover.
// ---------------------------------------------------------------------------
__global__ void node_proj_kernel(const float* __restrict__ node,
                                 const float* __restrict__ Wi,
                                 const float* __restrict__ bi) {
    __shared__ float s[4 * C_NODE];               // 6 KB
    const int t  = threadIdx.x;                   // 0..383
    const int r0 = blockIdx.x * 4;
    reinterpret_cast<float4*>(s)[t] =
        reinterpret_cast<const float4*>(node + (size_t)r0 * C_NODE)[t];
    __syncthreads();
    const int j  = t % C_BIAS;
    const int rh = t / C_BIAS;                    // 0 or 1
    const float* sr = s + rh * 2 * C_NODE;
    float a0 = 0.f, a1 = 0.f;
#pragma unroll 8
    for (int k = 0; k < C_NODE; k++) {
        const float w = Wi[k * C_BIAS + j];
        a0 += sr[k] * w;
        a1 += sr[C_NODE + k] * w;
    }
    const float bv = bi[j];
    g_n[(size_t)(r0 + rh * 2 + 0) * C_BIAS + j] = a0 + bv;
    g_n[(size_t)(r0 + rh * 2 + 1) * C_BIAS + j] = a1 + bv;
}

// ---------------------------------------------------------------------------
// Build X[b,i,k] = concat(edge(128), n[b,i](192), n[b,E_idx](192)) as fp16.
// ---------------------------------------------------------------------------
__global__ void build_x_kernel(const float* __restrict__ edge, const int* __restrict__ Eidx) {
    const int bi = blockIdx.x;
    __shared__ __align__(16) __half s_self[C_BIAS];
    __shared__ int s_idx[KNBR];
    const int t = threadIdx.x;
    if (t < C_BIAS) s_self[t] = __float2half_rn(g_n[(size_t)bi * C_BIAS + t]);
    if (t < KNBR)   s_idx[t]  = Eidx[bi * KNBR + t];
    __syncthreads();

    const int b = bi / NRES;
    const float* nb = g_n + (size_t)b * NRES * C_BIAS;
    const float* er = edge + (size_t)bi * KNBR * C_EDGE;
    __half* xr = g_X + (size_t)bi * KNBR * HID;

    for (int g = t; g < KNBR * (HID / 8); g += 256) {
        const int k  = g >> 6;
        const int c8 = (g & 63) * 8;
        uint4 w;
        if (c8 < C_EDGE) {
            const float4 a  = *reinterpret_cast<const float4*>(er + k * C_EDGE + c8);
            const float4 bq = *reinterpret_cast<const float4*>(er + k * C_EDGE + c8 + 4);
            __half2 h0 = __floats2half2_rn(a.x, a.y),  h1 = __floats2half2_rn(a.z, a.w);
            __half2 h2 = __floats2half2_rn(bq.x, bq.y), h3 = __floats2half2_rn(bq.z, bq.w);
            w = make_uint4(*(uint32_t*)&h0, *(uint32_t*)&h1, *(uint32_t*)&h2, *(uint32_t*)&h3);
        } else if (c8 < C_EDGE + C_BIAS) {
            w = *reinterpret_cast<const uint4*>(s_self + (c8 - C_EDGE));
        } else {
            const float* src = nb + (size_t)s_idx[k] * C_BIAS + (c8 - C_EDGE - C_BIAS);
            const float4 a  = *reinterpret_cast<const float4*>(src);
            const float4 bq = *reinterpret_cast<const float4*>(src + 4);
            __half2 h0 = __floats2half2_rn(a.x, a.y),  h1 = __floats2half2_rn(a.z, a.w);
            __half2 h2 = __floats2half2_rn(bq.x, bq.y), h3 = __floats2half2_rn(bq.z, bq.w);
            w = make_uint4(*(uint32_t*)&h0, *(uint32_t*)&h1, *(uint32_t*)&h2, *(uint32_t*)&h3);
        }
        *reinterpret_cast<uint4*>(xr + k * HID + c8) = w;
    }
}

// ---------------------------------------------------------------------------
// GEMM: C[M, Nc] = act( A @ Bw + bias ) [+ Xres],  K = KT*64 (lda=512, ldb=Nc).
// fp16 in / fp32 accumulate, mma.sync m16n8k16.
// BM=128, BN=128, BK=64; 256 threads (8 warps 4x2), warp tile 32x64.
// 3-stage cp.async pipeline, one __syncthreads per K-tile, 2 CTAs/SM.
// ADDX : epilogue out = relu(acc+bias) + Xres   (residual fold)
// LN_OUT: stage acc+bias to smem, fused LayerNorm (Nc==128).
// ---------------------------------------------------------------------------
template <bool RELU, bool LN_OUT, bool ADDX>
__global__ void __launch_bounds__(256, 2)
gemm_kernel(const __half* __restrict__ A, const __half* __restrict__ Bw,
            const float* __restrict__ bias, const __half* __restrict__ Xres,
            const float* __restrict__ gamma, const float* __restrict__ beta,
            __half* __restrict__ Ch, float* __restrict__ Cf,
            int Nc, int KT) {
    constexpr int BM = 128, BN = 128, BK = 64;
    constexpr int LDA = BK + 8;   // 72
    constexpr int LDB = BN + 8;   // 136
    extern __shared__ __align__(16) char smem_raw[];
    __half (*As)[BM][LDA] = reinterpret_cast<__half (*)[BM][LDA]>(smem_raw);
    __half (*Bs)[BK][LDB] = reinterpret_cast<__half (*)[BK][LDB]>(smem_raw + 3 * BM * LDA * 2);

    const int t = threadIdx.x, lane = t & 31, wid = t >> 5;
    const int bm = blockIdx.y, bn = blockIdx.x;
    const int wm = (wid >> 1) * 32, wn = (wid & 1) * 64;

    float acc[2][8][4];
#pragma unroll
    for (int a = 0; a < 2; a++)
#pragma unroll
        for (int b = 0; b < 8; b++)
#pragma unroll
            for (int c = 0; c < 4; c++) acc[a][b][c] = 0.f;

    auto load_tiles = [&](int st, int kt) {
        const int k0 = kt * BK;
#pragma unroll
        for (int j = 0; j < 4; j++) {                 // A: 1024 16B segs
            const int idx = j * 256 + t;
            const int r = idx >> 3, sg = idx & 7;
            const __half* src = A + ((size_t)bm * BM + r) * HID + k0 + sg * 8;
            const uint32_t dst = (uint32_t)__cvta_generic_to_shared(&As[st][r][sg * 8]);
            asm volatile("cp.async.cg.shared.global [%0], [%1], 16;\n" :: "r"(dst), "l"(src));
        }
#pragma unroll
        for (int j = 0; j < 4; j++) {                 // B: 1024 16B segs
            const int idx = j * 256 + t;
            const int r = idx >> 4, sg = idx & 15;
            const __half* src = Bw + (size_t)(k0 + r) * Nc + bn * BN + sg * 8;
            const uint32_t dst = (uint32_t)__cvta_generic_to_shared(&Bs[st][r][sg * 8]);
            asm volatile("cp.async.cg.shared.global [%0], [%1], 16;\n" :: "r"(dst), "l"(src));
        }
    };

    load_tiles(0, 0);
    asm volatile("cp.async.commit_group;\n");
    if (KT > 1) {
        load_tiles(1, 1);
        asm volatile("cp.async.commit_group;\n");
    }

    int st = 0;
    for (int kt = 0; kt < KT; kt++, st = (st == 2) ? 0 : st + 1) {
        if (kt < KT - 1) asm volatile("cp.async.wait_group 1;\n");
        else             asm volatile("cp.async.wait_group 0;\n");
        __syncthreads();
        if (kt + 2 < KT) {
            const int st2 = (st + 2 > 2) ? st - 1 : st + 2;
            load_tiles(st2, kt + 2);
            asm volatile("cp.async.commit_group;\n");
        }
#pragma unroll
        for (int kk = 0; kk < 4; kk++) {
            uint32_t afr[2][4];
#pragma unroll
            for (int mi = 0; mi < 2; mi++) {
                const uint32_t addr = (uint32_t)__cvta_generic_to_shared(
                    &As[st][wm + mi * 16 + (lane & 15)][kk * 16 + ((lane >> 4) << 3)]);
                asm volatile("ldmatrix.sync.aligned.m8n8.x4.shared.b16 {%0,%1,%2,%3}, [%4];\n"
                             : "=r"(afr[mi][0]), "=r"(afr[mi][1]), "=r"(afr[mi][2]), "=r"(afr[mi][3])
                             : "r"(addr));
            }
            uint32_t bfr[4][4];
#pragma unroll
            for (int nj = 0; nj < 4; nj++) {
                const uint32_t addr = (uint32_t)__cvta_generic_to_shared(
                    &Bs[st][kk * 16 + (lane & 15)][wn + nj * 16 + ((lane >> 4) << 3)]);
                asm volatile("ldmatrix.sync.aligned.m8n8.x4.trans.shared.b16 {%0,%1,%2,%3}, [%4];\n"
                             : "=r"(bfr[nj][0]), "=r"(bfr[nj][1]), "=r"(bfr[nj][2]), "=r"(bfr[nj][3])
                             : "r"(addr));
            }
#pragma unroll
            for (int mi = 0; mi < 2; mi++)
#pragma unroll
                for (int n8 = 0; n8 < 8; n8++) {
                    const uint32_t b0 = bfr[n8 >> 1][(n8 & 1) * 2 + 0];
                    const uint32_t b1 = bfr[n8 >> 1][(n8 & 1) * 2 + 1];
                    asm volatile(
                        "mma.sync.aligned.m16n8k16.row.col.f32.f16.f16.f32 "
                        "{%0,%1,%2,%3}, {%4,%5,%6,%7}, {%8,%9}, {%0,%1,%2,%3};\n"
                        : "+f"(acc[mi][n8][0]), "+f"(acc[mi][n8][1]),
                          "+f"(acc[mi][n8][2]), "+f"(acc[mi][n8][3])
                        : "r"(afr[mi][0]), "r"(afr[mi][1]), "r"(afr[mi][2]), "r"(afr[mi][3]),
                          "r"(b0), "r"(b1));
                }
        }
    }

    const int lr = lane >> 2, lc = (lane & 3) * 2;
    if (!LN_OUT) {
#pragma unroll
        for (int mi = 0; mi < 2; mi++) {
#pragma unroll
            for (int n8 = 0; n8 < 8; n8++) {
                const int row = bm * BM + wm + mi * 16 + lr;
                const int col = bn * BN + wn + n8 * 8 + lc;
                const float bv0 = bias[col], bv1 = bias[col + 1];
                float v0 = acc[mi][n8][0] + bv0;
                float v1 = acc[mi][n8][1] + bv1;
                float v2 = acc[mi][n8][2] + bv0;
                float v3 = acc[mi][n8][3] + bv1;
                if (RELU) {
                    v0 = fmaxf(v0, 0.f); v1 = fmaxf(v1, 0.f);
                    v2 = fmaxf(v2, 0.f); v3 = fmaxf(v3, 0.f);
                }
                if (ADDX) {
                    const __half2 x0 = *reinterpret_cast<const __half2*>(
                        Xres + (size_t)row * Nc + col);
                    const __half2 x1 = *reinterpret_cast<const __half2*>(
                        Xres + (size_t)(row + 8) * Nc + col);
                    v0 += __low2float(x0); v1 += __high2float(x0);
                    v2 += __low2float(x1); v3 += __high2float(x1);
                }
                *reinterpret_cast<__half2*>(Ch + (size_t)row * Nc + col)       = __floats2half2_rn(v0, v1);
                *reinterpret_cast<__half2*>(Ch + (size_t)(row + 8) * Nc + col) = __floats2half2_rn(v2, v3);
            }
        }
    } else {
        // stage acc+bias to smem, fused LayerNorm (Nc == 128, bn == 0)
        constexpr int LDY = 132;
        float* sY = reinterpret_cast<float*>(smem_raw);
        __syncthreads();
#pragma unroll
        for (int mi = 0; mi < 2; mi++) {
#pragma unroll
            for (int n8 = 0; n8 < 8; n8++) {
                const int r = wm + mi * 16 + lr;
                const int c = wn + n8 * 8 + lc;
                const float bv0 = bias[c], bv1 = bias[c + 1];
                *reinterpret_cast<float2*>(&sY[r * LDY + c]) =
                    make_float2(acc[mi][n8][0] + bv0, acc[mi][n8][1] + bv1);
                *reinterpret_cast<float2*>(&sY[(r + 8) * LDY + c]) =
                    make_float2(acc[mi][n8][2] + bv0, acc[mi][n8][3] + bv1);
            }
        }
        __syncthreads();
        const float4 gg = reinterpret_cast<const float4*>(gamma)[lane];
        const float4 bb = reinterpret_cast<const float4*>(beta)[lane];
#pragma unroll
        for (int rr = 0; rr < 16; rr++) {
            const int r = wid * 16 + rr;
            const float4 v = *reinterpret_cast<const float4*>(&sY[r * LDY + lane * 4]);
            float s  = v.x + v.y + v.z + v.w;
            float sq = v.x * v.x + v.y * v.y + v.z * v.z + v.w * v.w;
#pragma unroll
            for (int off = 16; off > 0; off >>= 1) {
                s  += __shfl_xor_sync(0xffffffffu, s, off);
                sq += __shfl_xor_sync(0xffffffffu, sq, off);
            }
            const float mu  = s * (1.f / 128.f);
            const float inv = rsqrtf(sq * (1.f / 128.f) - mu * mu + 1e-5f);
            float4 o;
            o.x = (v.x - mu) * inv * gg.x + bb.x;
            o.y = (v.y - mu) * inv * gg.y + bb.y;
            o.z = (v.z - mu) * inv * gg.z + bb.z;
            o.w = (v.w - mu) * inv * gg.w + bb.w;
            *reinterpret_cast<float4*>(Cf + (size_t)(bm * BM + r) * 128 + lane * 4) = o;
        }
    }
}

// ---------------------------------------------------------------------------
// Launch
// ---------------------------------------------------------------------------
extern "C" void kernel_launch(void* const* d_in, const int* in_sizes, int n_in,
                              void* d_out, int out_size) {
    const float* node  = (const float*)d_in[0];
    const float* edge  = (const float*)d_in[1];
    const int*   eidx  = (const int*)  d_in[2];
    const float* Wi    = (const float*)d_in[3];
    const float* bi    = (const float*)d_in[4];
    const float* W1    = (const float*)d_in[5];
    const float* b1    = (const float*)d_in[6];
    const float* W2    = (const float*)d_in[7];
    const float* b2    = (const float*)d_in[8];
    const float* Wf    = (const float*)d_in[9];
    const float* bf    = (const float*)d_in[10];
    const float* gamma = (const float*)d_in[11];
    const float* beta  = (const float*)d_in[12];
    float* out = (float*)d_out;

    void *pW1h, *pW2h, *pWfh, *pX, *pH, *pH2;
    cudaGetSymbolAddress(&pW1h, g_W1h);
    cudaGetSymbolAddress(&pW2h, g_W2h);
    cudaGetSymbolAddress(&pWfh, g_Wfh);
    cudaGetSymbolAddress(&pX,  g_X);
    cudaGetSymbolAddress(&pH,  g_H);
    cudaGetSymbolAddress(&pH2, g_H2);

    // dynamic smem: 3 stages of (As 128x72 + Bs 64x136) fp16
    const int SMEM = 3 * (128 * 72 + 64 * 136) * 2;   // 107,520 B
    cudaFuncSetAttribute(gemm_kernel<true,  false, false>,
                         cudaFuncAttributeMaxDynamicSharedMemorySize, SMEM);
    cudaFuncSetAttribute(gemm_kernel<true,  false, true>,
                         cudaFuncAttributeMaxDynamicSharedMemorySize, SMEM);
    cudaFuncSetAttribute(gemm_kernel<false, true,  false>,
                         cudaFuncAttributeMaxDynamicSharedMemorySize, SMEM);

    f2h_kernel<<<512, 256>>>(W1, (__half*)pW1h, HID * HID);      // launch 0
    f2h_kernel<<<512, 256>>>(W2, (__half*)pW2h, HID * HID);      // launch 1
    f2h_kernel<<<256, 256>>>(Wf, (__half*)pWfh, HID * C_OUT_);   // launch 2

    node_proj_kernel<<<NODES / 4, 384>>>(node, Wi, bi);          // launch 3
    build_x_kernel<<<NODES, 256>>>(edge, eidx);                  // launch 4

    // h = relu(X @ W1 + b1)                                        launch 5
    gemm_kernel<true, false, false><<<dim3(HID / 128, MROWS / 128), 256, SMEM>>>(
        (const __half*)pX, (const __half*)pW1h, b1, nullptr,
        nullptr, nullptr, (__half*)pH, nullptr, HID, 8);
    // h2' = relu(h @ W2 + b2) + x      (residual folded)            launch 6
    gemm_kernel<true, false, true><<<dim3(HID / 128, MROWS / 128), 256, SMEM>>>(
        (const __half*)pH, (const __half*)pW2h, b2, (const __half*)pX,
        nullptr, nullptr, (__half*)pH2, nullptr, HID, 8);
    // out = LN(h2' @ Wf + bf)          (single-A K=512, fused LN)   launch 7
    gemm_kernel<false, true, false><<<dim3(1, MROWS / 128), 256, SMEM>>>(
        (const __half*)pH2, (const __half*)pWfh, bf, nullptr,
        gamma, beta, nullptr, out, C_OUT_, 8);
}

// round 9
// speedup vs baseline: 1.8282x; 1.1511x over previous
#include <cuda_runtime.h>
#include <cuda_fp16.h>
#include <cstdint>

// ---------------------------------------------------------------------------
// Problem constants
// ---------------------------------------------------------------------------
#define BATCH   2
#define NRES    1280
#define KNBR    48
#define C_NODE  384
#define C_EDGE  128
#define C_OUT_  128
#define C_BIAS  192
#define HID     512
#define NODES   (BATCH * NRES)        // 2560
#define MROWS   (NODES * KNBR)        // 122880 = 960 * 128

// ---------------------------------------------------------------------------
// Scratch (static device globals; allocation-free per harness rules)
// ---------------------------------------------------------------------------
__device__ float  g_n  [NODES * C_BIAS];             // node projection fp32
__device__ __half g_nh [NODES * C_BIAS];             // node projection fp16
__device__ __half g_X  [(size_t)MROWS * HID];        // concat input rows
__device__ __half g_H  [(size_t)MROWS * HID];        // relu(x@W1+b1)
__device__ __half g_H2 [(size_t)MROWS * HID];        // relu(h@W2+b2) + x
__device__ __half g_P  [(size_t)NODES * 1024];       // [PS(512) | PN(512)] per node
__device__ __half g_W1e[C_EDGE * HID];               // W1 rows 0:128   [128][512]
__device__ __half g_Wsn[C_BIAS * 1024];              // [W1s | W1n]     [192][1024]
__device__ __half g_W2h[HID * HID];
__device__ __half g_Wfh[HID * C_OUT_];
__device__ float  g_zero[1024];                      // zero-init bias

// ---------------------------------------------------------------------------
// fp32 -> fp16 weight conversion
// ---------------------------------------------------------------------------
__global__ void f2h_kernel(const float* __restrict__ src, __half* __restrict__ dst, int n) {
    for (int i = blockIdx.x * blockDim.x + threadIdx.x; i < n; i += gridDim.x * blockDim.x)
        dst[i] = __float2half_rn(src[i]);
}

// ---------------------------------------------------------------------------
// Pack W1 [512][512] fp32 into W1e [128][512] fp16 (rows 0:128) and
// Wsn [192][1024] fp16 (Wsn[k][n] = W1[128+k][n]; Wsn[k][512+n] = W1[320+k][n])
// ---------------------------------------------------------------------------
__global__ void prep_w1_kernel(const float* __restrict__ W1) {
    const int i = blockIdx.x * blockDim.x + threadIdx.x;   // 0 .. 262143
    if (i < C_EDGE * HID) {
        g_W1e[i] = __float2half_rn(W1[i]);                 // rows 0:128 verbatim
    } else {
        const int j = i - C_EDGE * HID;                    // 0 .. 196607
        const int k = j >> 10, n = j & 1023;
        const int src_row = (n < HID) ? (128 + k) : (320 + k);
        const int src_col = (n < HID) ? n : (n - HID);
        g_Wsn[j] = __float2half_rn(W1[src_row * HID + src_col]);
    }
}

// ---------------------------------------------------------------------------
// n = node_emb @ Wi + bi   [2560,384]@[384,192]
// 640 blocks x 384 threads; 4 rows/block; thread = (col-pair, row).
// Writes fp32 (for build_x) and fp16 (for P-GEMM A operand).
// ---------------------------------------------------------------------------
__global__ void node_proj_kernel(const float* __restrict__ node,
                                 const float* __restrict__ Wi,
                                 const float* __restrict__ bi) {
    __shared__ float s[4 * C_NODE];               // 6 KB
    const int t  = threadIdx.x;                   // 0..383
    const int r0 = blockIdx.x * 4;
    reinterpret_cast<float4*>(s)[t] =
        reinterpret_cast<const float4*>(node + (size_t)r0 * C_NODE)[t];
    __syncthreads();
    const int jp = t % 96, rh = t / 96;           // col-pair 0..95, row 0..3
    const int j0 = jp * 2;
    const float* sr = s + rh * C_NODE;
    float a0 = 0.f, a1 = 0.f;
#pragma unroll 8
    for (int k = 0; k < C_NODE; k++) {
        const float2 w = *reinterpret_cast<const float2*>(Wi + k * C_BIAS + j0);
        const float sv = sr[k];
        a0 += sv * w.x;
        a1 += sv * w.y;
    }
    a0 += bi[j0];
    a1 += bi[j0 + 1];
    const size_t o = (size_t)(r0 + rh) * C_BIAS + j0;
    g_n[o] = a0; g_n[o + 1] = a1;
    *reinterpret_cast<__half2*>(g_nh + o) = __floats2half2_rn(a0, a1);
}

// ---------------------------------------------------------------------------
// Build X[b,i,k] = concat(edge(128), n[b,i](192), n[b,E_idx](192)) as fp16.
// ---------------------------------------------------------------------------
__global__ void build_x_kernel(const float* __restrict__ edge, const int* __restrict__ Eidx) {
    const int bi = blockIdx.x;
    __shared__ __align__(16) __half s_self[C_BIAS];
    __shared__ int s_idx[KNBR];
    const int t = threadIdx.x;
    if (t < C_BIAS) s_self[t] = __float2half_rn(g_n[(size_t)bi * C_BIAS + t]);
    if (t < KNBR)   s_idx[t]  = Eidx[bi * KNBR + t];
    __syncthreads();

    const int b = bi / NRES;
    const float* nb = g_n + (size_t)b * NRES * C_BIAS;
    const float* er = edge + (size_t)bi * KNBR * C_EDGE;
    __half* xr = g_X + (size_t)bi * KNBR * HID;

    for (int g = t; g < KNBR * (HID / 8); g += 256) {
        const int k  = g >> 6;
        const int c8 = (g & 63) * 8;
        uint4 w;
        if (c8 < C_EDGE) {
            const float4 a  = *reinterpret_cast<const float4*>(er + k * C_EDGE + c8);
            const float4 bq = *reinterpret_cast<const float4*>(er + k * C_EDGE + c8 + 4);
            __half2 h0 = __floats2half2_rn(a.x, a.y),  h1 = __floats2half2_rn(a.z, a.w);
            __half2 h2 = __floats2half2_rn(bq.x, bq.y), h3 = __floats2half2_rn(bq.z, bq.w);
            w = make_uint4(*(uint32_t*)&h0, *(uint32_t*)&h1, *(uint32_t*)&h2, *(uint32_t*)&h3);
        } else if (c8 < C_EDGE + C_BIAS) {
            w = *reinterpret_cast<const uint4*>(s_self + (c8 - C_EDGE));
        } else {
            const float* src = nb + (size_t)s_idx[k] * C_BIAS + (c8 - C_EDGE - C_BIAS);
            const float4 a  = *reinterpret_cast<const float4*>(src);
            const float4 bq = *reinterpret_cast<const float4*>(src + 4);
            __half2 h0 = __floats2half2_rn(a.x, a.y),  h1 = __floats2half2_rn(a.z, a.w);
            __half2 h2 = __floats2half2_rn(bq.x, bq.y), h3 = __floats2half2_rn(bq.z, bq.w);
            w = make_uint4(*(uint32_t*)&h0, *(uint32_t*)&h1, *(uint32_t*)&h2, *(uint32_t*)&h3);
        }
        *reinterpret_cast<uint4*>(xr + k * HID + c8) = w;
    }
}

// ---------------------------------------------------------------------------
// GEMM: C[M, Nc] = act( A @ Bw + bias [+ gather] ) [+ Xres]
// A row-major [M][lda], K = KT*64. fp16 in / fp32 acc, mma.sync m16n8k16.
// BM=128, BN=128, BK=64; 256 threads (8 warps 4x2), warp tile 32x64.
// 3-stage cp.async pipeline, one __syncthreads per K-tile, 2 CTAs/SM.
// GATHER: epilogue adds PS[m/48][col] + PN[b*1280+Eidx[m]][col] (fp16, L2-res)
// ADDX  : epilogue adds Xres row (residual fold)
// LN_OUT: stage acc+bias to smem, fused LayerNorm (Nc==128)
// ---------------------------------------------------------------------------
template <bool RELU, bool LN_OUT, bool ADDX, bool GATHER>
__global__ void __launch_bounds__(256, 2)
gemm_kernel(const __half* __restrict__ A, const __half* __restrict__ Bw,
            const float* __restrict__ bias, const __half* __restrict__ Xres,
            const int* __restrict__ Eidx, const __half* __restrict__ Pp,
            const float* __restrict__ gamma, const float* __restrict__ beta,
            __half* __restrict__ Ch, float* __restrict__ Cf,
            int Nc, int KT, int lda) {
    constexpr int BM = 128, BN = 128, BK = 64;
    constexpr int LDA = BK + 8;   // 72
    constexpr int LDB = BN + 8;   // 136
    extern __shared__ __align__(16) char smem_raw[];
    __half (*As)[BM][LDA] = reinterpret_cast<__half (*)[BM][LDA]>(smem_raw);
    __half (*Bs)[BK][LDB] = reinterpret_cast<__half (*)[BK][LDB]>(smem_raw + 3 * BM * LDA * 2);

    const int t = threadIdx.x, lane = t & 31, wid = t >> 5;
    const int bm = blockIdx.y, bn = blockIdx.x;
    const int wm = (wid >> 1) * 32, wn = (wid & 1) * 64;

    float acc[2][8][4];
#pragma unroll
    for (int a = 0; a < 2; a++)
#pragma unroll
        for (int b = 0; b < 8; b++)
#pragma unroll
            for (int c = 0; c < 4; c++) acc[a][b][c] = 0.f;

    auto load_tiles = [&](int st, int kt) {
        const int k0 = kt * BK;
#pragma unroll
        for (int j = 0; j < 4; j++) {                 // A: 1024 16B segs
            const int idx = j * 256 + t;
            const int r = idx >> 3, sg = idx & 7;
            const __half* src = A + ((size_t)bm * BM + r) * lda + k0 + sg * 8;
            const uint32_t dst = (uint32_t)__cvta_generic_to_shared(&As[st][r][sg * 8]);
            asm volatile("cp.async.cg.shared.global [%0], [%1], 16;\n" :: "r"(dst), "l"(src));
        }
#pragma unroll
        for (int j = 0; j < 4; j++) {                 // B: 1024 16B segs
            const int idx = j * 256 + t;
            const int r = idx >> 4, sg = idx & 15;
            const __half* src = Bw + (size_t)(k0 + r) * Nc + bn * BN + sg * 8;
            const uint32_t dst = (uint32_t)__cvta_generic_to_shared(&Bs[st][r][sg * 8]);
            asm volatile("cp.async.cg.shared.global [%0], [%1], 16;\n" :: "r"(dst), "l"(src));
        }
    };

    load_tiles(0, 0);
    asm volatile("cp.async.commit_group;\n");
    if (KT > 1) {
        load_tiles(1, 1);
        asm volatile("cp.async.commit_group;\n");
    }

    int st = 0;
    for (int kt = 0; kt < KT; kt++, st = (st == 2) ? 0 : st + 1) {
        if (kt < KT - 1) asm volatile("cp.async.wait_group 1;\n");
        else             asm volatile("cp.async.wait_group 0;\n");
        __syncthreads();
        if (kt + 2 < KT) {
            const int st2 = (st + 2 > 2) ? st - 1 : st + 2;
            load_tiles(st2, kt + 2);
            asm volatile("cp.async.commit_group;\n");
        }
#pragma unroll
        for (int kk = 0; kk < 4; kk++) {
            uint32_t afr[2][4];
#pragma unroll
            for (int mi = 0; mi < 2; mi++) {
                const uint32_t addr = (uint32_t)__cvta_generic_to_shared(
                    &As[st][wm + mi * 16 + (lane & 15)][kk * 16 + ((lane >> 4) << 3)]);
                asm volatile("ldmatrix.sync.aligned.m8n8.x4.shared.b16 {%0,%1,%2,%3}, [%4];\n"
                             : "=r"(afr[mi][0]), "=r"(afr[mi][1]), "=r"(afr[mi][2]), "=r"(afr[mi][3])
                             : "r"(addr));
            }
            uint32_t bfr[4][4];
#pragma unroll
            for (int nj = 0; nj < 4; nj++) {
                const uint32_t addr = (uint32_t)__cvta_generic_to_shared(
                    &Bs[st][kk * 16 + (lane & 15)][wn + nj * 16 + ((lane >> 4) << 3)]);
                asm volatile("ldmatrix.sync.aligned.m8n8.x4.trans.shared.b16 {%0,%1,%2,%3}, [%4];\n"
                             : "=r"(bfr[nj][0]), "=r"(bfr[nj][1]), "=r"(bfr[nj][2]), "=r"(bfr[nj][3])
                             : "r"(addr));
            }
#pragma unroll
            for (int mi = 0; mi < 2; mi++)
#pragma unroll
                for (int n8 = 0; n8 < 8; n8++) {
                    const uint32_t b0 = bfr[n8 >> 1][(n8 & 1) * 2 + 0];
                    const uint32_t b1 = bfr[n8 >> 1][(n8 & 1) * 2 + 1];
                    asm volatile(
                        "mma.sync.aligned.m16n8k16.row.col.f32.f16.f16.f32 "
                        "{%0,%1,%2,%3}, {%4,%5,%6,%7}, {%8,%9}, {%0,%1,%2,%3};\n"
                        : "+f"(acc[mi][n8][0]), "+f"(acc[mi][n8][1]),
                          "+f"(acc[mi][n8][2]), "+f"(acc[mi][n8][3])
                        : "r"(afr[mi][0]), "r"(afr[mi][1]), "r"(afr[mi][2]), "r"(afr[mi][3]),
                          "r"(b0), "r"(b1));
                }
        }
    }

    const int lr = lane >> 2, lc = (lane & 3) * 2;
    if (!LN_OUT) {
#pragma unroll
        for (int mi = 0; mi < 2; mi++) {
            const int rowA = bm * BM + wm + mi * 16 + lr;
            const int rowB = rowA + 8;
            const __half *psA = nullptr, *psB = nullptr, *pnA = nullptr, *pnB = nullptr;
            if (GATHER) {
                psA = Pp + (size_t)(rowA / KNBR) * 1024;
                psB = Pp + (size_t)(rowB / KNBR) * 1024;
                const int bA = rowA / (NRES * KNBR), bB = rowB / (NRES * KNBR);
                pnA = Pp + ((size_t)(bA * NRES + Eidx[rowA])) * 1024 + 512;
                pnB = Pp + ((size_t)(bB * NRES + Eidx[rowB])) * 1024 + 512;
            }
#pragma unroll
            for (int n8 = 0; n8 < 8; n8++) {
                const int col = bn * BN + wn + n8 * 8 + lc;
                const float bv0 = bias[col], bv1 = bias[col + 1];
                float v0 = acc[mi][n8][0] + bv0;
                float v1 = acc[mi][n8][1] + bv1;
                float v2 = acc[mi][n8][2] + bv0;
                float v3 = acc[mi][n8][3] + bv1;
                if (GATHER) {
                    const __half2 sA = *reinterpret_cast<const __half2*>(psA + col);
                    const __half2 sB = *reinterpret_cast<const __half2*>(psB + col);
                    const __half2 gA = *reinterpret_cast<const __half2*>(pnA + col);
                    const __half2 gB = *reinterpret_cast<const __half2*>(pnB + col);
                    v0 += __low2float(sA) + __low2float(gA);
                    v1 += __high2float(sA) + __high2float(gA);
                    v2 += __low2float(sB) + __low2float(gB);
                    v3 += __high2float(sB) + __high2float(gB);
                }
                if (RELU) {
                    v0 = fmaxf(v0, 0.f); v1 = fmaxf(v1, 0.f);
                    v2 = fmaxf(v2, 0.f); v3 = fmaxf(v3, 0.f);
                }
                if (ADDX) {
                    const __half2 x0 = *reinterpret_cast<const __half2*>(
                        Xres + (size_t)rowA * Nc + col);
                    const __half2 x1 = *reinterpret_cast<const __half2*>(
                        Xres + (size_t)rowB * Nc + col);
                    v0 += __low2float(x0); v1 += __high2float(x0);
                    v2 += __low2float(x1); v3 += __high2float(x1);
                }
                *reinterpret_cast<__half2*>(Ch + (size_t)rowA * Nc + col) = __floats2half2_rn(v0, v1);
                *reinterpret_cast<__half2*>(Ch + (size_t)rowB * Nc + col) = __floats2half2_rn(v2, v3);
            }
        }
    } else {
        // stage acc+bias to smem, fused LayerNorm (Nc == 128, bn == 0)
        constexpr int LDY = 132;
        float* sY = reinterpret_cast<float*>(smem_raw);
        __syncthreads();
#pragma unroll
        for (int mi = 0; mi < 2; mi++) {
#pragma unroll
            for (int n8 = 0; n8 < 8; n8++) {
                const int r = wm + mi * 16 + lr;
                const int c = wn + n8 * 8 + lc;
                const float bv0 = bias[c], bv1 = bias[c + 1];
                *reinterpret_cast<float2*>(&sY[r * LDY + c]) =
                    make_float2(acc[mi][n8][0] + bv0, acc[mi][n8][1] + bv1);
                *reinterpret_cast<float2*>(&sY[(r + 8) * LDY + c]) =
                    make_float2(acc[mi][n8][2] + bv0, acc[mi][n8][3] + bv1);
            }
        }
        __syncthreads();
        const float4 gg = reinterpret_cast<const float4*>(gamma)[lane];
        const float4 bb = reinterpret_cast<const float4*>(beta)[lane];
#pragma unroll
        for (int rr = 0; rr < 16; rr++) {
            const int r = wid * 16 + rr;
            const float4 v = *reinterpret_cast<const float4*>(&sY[r * LDY + lane * 4]);
            float s  = v.x + v.y + v.z + v.w;
            float sq = v.x * v.x + v.y * v.y + v.z * v.z + v.w * v.w;
#pragma unroll
            for (int off = 16; off > 0; off >>= 1) {
                s  += __shfl_xor_sync(0xffffffffu, s, off);
                sq += __shfl_xor_sync(0xffffffffu, sq, off);
            }
            const float mu  = s * (1.f / 128.f);
            const float inv = rsqrtf(sq * (1.f / 128.f) - mu * mu + 1e-5f);
            float4 o;
            o.x = (v.x - mu) * inv * gg.x + bb.x;
            o.y = (v.y - mu) * inv * gg.y + bb.y;
            o.z = (v.z - mu) * inv * gg.z + bb.z;
            o.w = (v.w - mu) * inv * gg.w + bb.w;
            *reinterpret_cast<float4*>(Cf + (size_t)(bm * BM + r) * 128 + lane * 4) = o;
        }
    }
}

// ---------------------------------------------------------------------------
// Launch
// ---------------------------------------------------------------------------
extern "C" void kernel_launch(void* const* d_in, const int* in_sizes, int n_in,
                              void* d_out, int out_size) {
    const float* node  = (const float*)d_in[0];
    const float* edge  = (const float*)d_in[1];
    const int*   eidx  = (const int*)  d_in[2];
    const float* Wi    = (const float*)d_in[3];
    const float* bi    = (const float*)d_in[4];
    const float* W1    = (const float*)d_in[5];
    const float* b1    = (const float*)d_in[6];
    const float* W2    = (const float*)d_in[7];
    const float* b2    = (const float*)d_in[8];
    const float* Wf    = (const float*)d_in[9];
    const float* bf    = (const float*)d_in[10];
    const float* gamma = (const float*)d_in[11];
    const float* beta  = (const float*)d_in[12];
    float* out = (float*)d_out;

    void *pW1e, *pWsn, *pW2h, *pWfh, *pX, *pH, *pH2, *pNh, *pP, *pZ;
    cudaGetSymbolAddress(&pW1e, g_W1e);
    cudaGetSymbolAddress(&pWsn, g_Wsn);
    cudaGetSymbolAddress(&pW2h, g_W2h);
    cudaGetSymbolAddress(&pWfh, g_Wfh);
    cudaGetSymbolAddress(&pX,   g_X);
    cudaGetSymbolAddress(&pH,   g_H);
    cudaGetSymbolAddress(&pH2,  g_H2);
    cudaGetSymbolAddress(&pNh,  g_nh);
    cudaGetSymbolAddress(&pP,   g_P);
    cudaGetSymbolAddress(&pZ,   g_zero);

    // dynamic smem: 3 stages of (As 128x72 + Bs 64x136) fp16
    const int SMEM = 3 * (128 * 72 + 64 * 136) * 2;   // 107,520 B
    cudaFuncSetAttribute(gemm_kernel<false, false, false, false>,
                         cudaFuncAttributeMaxDynamicSharedMemorySize, SMEM);
    cudaFuncSetAttribute(gemm_kernel<true,  false, false, true>,
                         cudaFuncAttributeMaxDynamicSharedMemorySize, SMEM);
    cudaFuncSetAttribute(gemm_kernel<true,  false, true,  false>,
                         cudaFuncAttributeMaxDynamicSharedMemorySize, SMEM);
    cudaFuncSetAttribute(gemm_kernel<false, true,  false, false>,
                         cudaFuncAttributeMaxDynamicSharedMemorySize, SMEM);

    node_proj_kernel<<<NODES / 4, 384>>>(node, Wi, bi);          // 0
    prep_w1_kernel<<<1024, 256>>>(W1);                            // 1
    // P = n @ [W1s|W1n]   [2560,192]@[192,1024] -> fp16
    gemm_kernel<false, false, false, false><<<dim3(8, NODES / 128), 256, SMEM>>>(
        (const __half*)pNh, (const __half*)pWsn, (const float*)pZ, nullptr,
        nullptr, nullptr, nullptr, nullptr, (__half*)pP, nullptr,
        1024, 3, C_BIAS);                                        // 2
    build_x_kernel<<<NODES, 256>>>(edge, eidx);                  // 3  (profiled slot)
    // h = relu(edge @ W1e + b1 + PS[m/48] + PN[gather])          4
    gemm_kernel<true, false, false, true><<<dim3(4, MROWS / 128), 256, SMEM>>>(
        (const __half*)pX, (const __half*)pW1e, b1, nullptr,
        eidx, (const __half*)pP, nullptr, nullptr, (__half*)pH, nullptr,
        HID, 2, HID);
    f2h_kernel<<<512, 256>>>(W2, (__half*)pW2h, HID * HID);      // 5
    // h2' = relu(h @ W2 + b2) + x                                 6
    gemm_kernel<true, false, true, false><<<dim3(4, MROWS / 128), 256, SMEM>>>(
        (const __half*)pH, (const __half*)pW2h, b2, (const __half*)pX,
        nullptr, nullptr, nullptr, nullptr, (__half*)pH2, nullptr,
        HID, 8, HID);
    f2h_kernel<<<256, 256>>>(Wf, (__half*)pWfh, HID * C_OUT_);   // 7
    // out = LN(h2' @ Wf + bf)                                     8
    gemm_kernel<false, true, false, false><<<dim3(1, MROWS / 128), 256, SMEM>>>(
        (const __half*)pH2, (const __half*)pWfh, bf, nullptr,
        nullptr, nullptr, gamma, beta, nullptr, out,
        C_OUT_, 8, HID);
}